// round 13
// baseline (speedup 1.0000x reference)
#include <cuda_runtime.h>
#include <cstdint>

#define BB      1024
#define MAXLEN  200
#define FF      64
#define DD      64
#define NT      256
#define GRID    304                        // ~2 persistent CTAs per SM
#define KT      (MAXLEN * DD)              // 12800 floats per k tile
#define KU      3200                       // 16B units per k tile
#define MAXB    4                          // max batches per CTA
// smem floats: 2*KT + spart 16*64 + su 64 + sub MAXB*64 + swr 16 + slen 4
#define SMEM2_FLOATS (2 * KT + 16 * DD + DD + MAXB * DD + 16 + 4)
#define SMEM2_BYTES  (SMEM2_FLOATS * 4)    // 107,872 B -> 2 CTAs/SM

__device__ float g_u[BB * DD];             // 256 KB scratch: u per batch

__device__ __forceinline__ void cp_async16(uint32_t saddr, const void* gaddr) {
    asm volatile("cp.async.cg.shared.global [%0], [%1], 16;" :: "r"(saddr), "l"(gaddr) : "memory");
}
__device__ __forceinline__ void cp_commit() {
    asm volatile("cp.async.commit_group;" ::: "memory");
}
template<int N> __device__ __forceinline__ void cp_wait() {
    asm volatile("cp.async.wait_group %0;" :: "n"(N) : "memory");
}
__device__ __forceinline__ float fast_sigmoid(float x) {
    float t;
    asm("tanh.approx.f32 %0, %1;" : "=f"(t) : "f"(0.5f * x));
    return fmaf(0.5f, t, 0.5f);
}
__device__ __forceinline__ float fast_exp8(float x) {   // exp(x/8)
    float e;
    asm("ex2.approx.f32 %0, %1;" : "=f"(e) : "f"(x * 0.18033688011112042f));
    return e;
}
__device__ __forceinline__ void stage_k(uint32_t sbk, const float* kb, int tid) {
    const char* gk = (const char*)kb;
#pragma unroll
    for (int r = 0; r < 12; ++r) {
        int u = tid + r * NT;
        cp_async16(sbk + u * 16, gk + (size_t)u * 16);
    }
    if (tid < KU - 12 * NT)                // 3200 - 3072 = 128 remainder
        cp_async16(sbk + (tid + 12 * NT) * 16, gk + (size_t)(tid + 12 * NT) * 16);
    cp_commit();
}

// ================= Kernel 1: u[b] = ((fs.q[b]) @ Wq) @ Wk^T =================
__global__ __launch_bounds__(NT, 8)
void u_kernel(const float* __restrict__ q,
              const float* __restrict__ fs,
              const float* __restrict__ Wq,
              const float* __restrict__ Wk) {
    __shared__ float spart[16 * DD];
    __shared__ float squ[DD];
    __shared__ float stmp[DD];

    const int b   = blockIdx.x;
    const int tid = threadIdx.x;
    const int hw  = tid >> 4;
    const int l16 = tid & 15;

    // qbar[d] = sum_f fs[f] * q[b,f,d]
    {
        const float4* qb4 = (const float4*)(q + (size_t)b * FF * DD);
        float4 a = make_float4(0.f, 0.f, 0.f, 0.f);
#pragma unroll
        for (int fi = 0; fi < 4; ++fi) {
            int f = hw + 16 * fi;
            float s = fs[f];
            float4 v = qb4[f * 16 + l16];
            a.x += s * v.x; a.y += s * v.y; a.z += s * v.z; a.w += s * v.w;
        }
        ((float4*)spart)[hw * 16 + l16] = a;
    }
    __syncthreads();
    if (tid < DD) {
        float s = 0.f;
#pragma unroll
        for (int i = 0; i < 16; ++i) s += spart[i * DD + tid];
        squ[tid] = s;
    }
    __syncthreads();

    // tmp[e] = sum_c qbar[c] * Wq[c,e]
    {
        float4 a = make_float4(0.f, 0.f, 0.f, 0.f);
#pragma unroll
        for (int ci = 0; ci < 4; ++ci) {
            int c = hw * 4 + ci;
            float s = squ[c];
            float4 v = ((const float4*)Wq)[c * 16 + l16];
            a.x += s * v.x; a.y += s * v.y; a.z += s * v.z; a.w += s * v.w;
        }
        ((float4*)spart)[hw * 16 + l16] = a;
    }
    __syncthreads();
    if (tid < DD) {
        float s = 0.f;
#pragma unroll
        for (int i = 0; i < 16; ++i) s += spart[i * DD + tid];
        stmp[tid] = s;
    }
    __syncthreads();

    // u[row] = sum_e tmp[e] * Wk[row,e]
    {
        float4 tv = ((const float4*)stmp)[l16];
#pragma unroll
        for (int r = 0; r < 4; ++r) {
            int row = hw + 16 * r;
            float4 wv = ((const float4*)(Wk + row * DD))[l16];
            float p = wv.x * tv.x + wv.y * tv.y + wv.z * tv.z + wv.w * tv.w;
#pragma unroll
            for (int o = 8; o; o >>= 1)
                p += __shfl_xor_sync(0xffffffffu, p, o);
            if (l16 == 0) g_u[b * DD + row] = p;
        }
    }
}

// ======= Kernel 2: persistent CTAs, cross-batch double-buffered pipeline =======
__global__ __launch_bounds__(NT, 4)     // minBlocks=4 forces regs<=64; smem limits to 2/SM
void score_kernel(const float* __restrict__ k,
                  const int*   __restrict__ kes_length,
                  const float* __restrict__ bias,
                  const float* __restrict__ Wv,
                  float*       __restrict__ out) {
    extern __shared__ float smd[];
    float* kb0   = smd;                    // k tile buffer 0
    float* kb1   = smd + KT;               // k tile buffer 1
    float* spart = smd + 2 * KT;           // 16*64 partials
    float* su    = spart + 16 * DD;        // w
    float* sub   = su + DD;                // MAXB x 64 : prefetched u vectors
    float* swr   = sub + MAXB * DD;        // 16 exp-sums
    int*   slen  = (int*)(swr + 16);       // MAXB lengths

    const int bid = blockIdx.x;
    const int tid = threadIdx.x;
    const int hw  = tid >> 4;              // half-warp id 0..15
    const int l16 = tid & 15;
    const int nb  = (BB - bid + GRID - 1) / GRID;   // 3 or 4 batches

    // ---- prefetch ALL tiny data BEFORE any cp.async (so LDGs don't queue) ----
    for (int i = tid; i < nb * 16; i += NT) {
        int j = i >> 4, comp = i & 15;
        ((float4*)sub)[i] = ((const float4*)(g_u + (size_t)(bid + j * GRID) * DD))[comp];
    }
    if (tid < nb) slen[tid] = kes_length[bid + tid * GRID];
    const float biasD = bias[0] * (float)DD;

    // ---- prime pipeline: stage batches 0 and 1 ----
    const uint32_t sa0 = (uint32_t)__cvta_generic_to_shared(kb0);
    const uint32_t sa1 = (uint32_t)__cvta_generic_to_shared(kb1);
    stage_k(sa0, k + (size_t)bid * KT, tid);
    if (nb > 1) stage_k(sa1, k + (size_t)(bid + GRID) * KT, tid);

#pragma unroll 1
    for (int j = 0; j < nb; ++j) {
        if (j + 1 < nb) cp_wait<1>(); else cp_wait<0>();
        __syncthreads();                    // tile j visible; spart free

        const float4* kt4 = (const float4*)((j & 1) ? kb1 : kb0);
        const float4  uv  = ((const float4*)(sub + j * DD))[l16];
        const int   len   = slen[j];
        const float mfill = (len == 0) ? 1.f : 0.f;

        float4 wa   = make_float4(0.f, 0.f, 0.f, 0.f);
        float  esum = 0.f;
#pragma unroll
        for (int i = 0; i < 13; ++i) {
            int t = hw + (i << 4);
            if (t < MAXLEN) {
                float4 kv = kt4[t * 16 + l16];
                float p = kv.x * uv.x + kv.y * uv.y + kv.z * uv.z + kv.w * uv.w;
#pragma unroll
                for (int o = 8; o; o >>= 1)
                    p += __shfl_xor_sync(0xffffffffu, p, o);   // 16-lane reduce
                float e = (t < len) ? fast_exp8(fast_sigmoid(p + biasD)) : mfill;
                wa.x += e * kv.x; wa.y += e * kv.y;
                wa.z += e * kv.z; wa.w += e * kv.w;
                esum += e;
            }
        }

        ((float4*)spart)[hw * 16 + l16] = wa;
        if (l16 == 0) swr[hw] = esum;
        __syncthreads();                    // all kbuf reads for batch j done

        // ---- refill the just-freed buffer with batch j+2 (DMA overlaps epilogue
        //      of j and the whole compute of j+1) ----
        if (j + 2 < nb)
            stage_k((j & 1) ? sa1 : sa0, k + (size_t)(bid + (j + 2) * GRID) * KT, tid);

        if (tid < DD) {
            float s = 0.f;
#pragma unroll
            for (int i = 0; i < 16; ++i) s += spart[i * DD + tid];
            su[tid] = s;
        }
        __syncthreads();

        // out[b,e] = inv * sum_c w[c] * Wv[c,e]
        {
            float4 a = make_float4(0.f, 0.f, 0.f, 0.f);
#pragma unroll
            for (int ci = 0; ci < 4; ++ci) {
                int c = hw * 4 + ci;
                float s = su[c];
                float4 v = ((const float4*)Wv)[c * 16 + l16];
                a.x += s * v.x; a.y += s * v.y; a.z += s * v.z; a.w += s * v.w;
            }
            ((float4*)spart)[hw * 16 + l16] = a;
        }
        __syncthreads();
        if (tid < DD) {
            float tot = 0.f;
#pragma unroll
            for (int i = 0; i < 16; ++i) tot += swr[i];
            float s = 0.f;
#pragma unroll
            for (int i = 0; i < 16; ++i) s += spart[i * DD + tid];
            out[(size_t)(bid + j * GRID) * DD + tid] = s * (1.f / tot);
        }
        // next iteration's top wait+sync guards spart/swr reuse
    }
}

extern "C" void kernel_launch(void* const* d_in, const int* in_sizes, int n_in,
                              void* d_out, int out_size) {
    const float* q    = (const float*)d_in[0];
    const float* k    = (const float*)d_in[1];
    // d_in[2] = v : unused by the reference computation
    const int*   kes  = (const int*)  d_in[3];
    const float* fs   = (const float*)d_in[4];
    const float* bias = (const float*)d_in[5];
    const float* Wq   = (const float*)d_in[6];
    const float* Wk   = (const float*)d_in[7];
    const float* Wv   = (const float*)d_in[8];
    float*       out  = (float*)d_out;

    cudaFuncSetAttribute(score_kernel, cudaFuncAttributePreferredSharedMemoryCarveout, 100);
    cudaFuncSetAttribute(score_kernel, cudaFuncAttributeMaxDynamicSharedMemorySize, SMEM2_BYTES);

    u_kernel<<<BB, NT>>>(q, fs, Wq, Wk);
    score_kernel<<<GRID, NT, SMEM2_BYTES>>>(k, kes, bias, Wv, out);
}

// round 14
// speedup vs baseline: 1.2022x; 1.2022x over previous
#include <cuda_runtime.h>
#include <cstdint>

#define BB      1024
#define MAXLEN  200
#define FF      64
#define DD      64
#define NT      256
#define KT      (MAXLEN * DD)              // 12800 floats per k tile

__device__ float g_u[BB * DD];             // 256 KB scratch: u per batch

__device__ __forceinline__ float fast_sigmoid(float x) {
    float t;
    asm("tanh.approx.f32 %0, %1;" : "=f"(t) : "f"(0.5f * x));
    return fmaf(0.5f, t, 0.5f);
}
__device__ __forceinline__ float fast_exp8(float x) {   // exp(x/8)
    float e;
    asm("ex2.approx.f32 %0, %1;" : "=f"(e) : "f"(x * 0.18033688011112042f));
    return e;
}

// ================= Kernel 1: u[b] = ((fs.q[b]) @ Wq) @ Wk^T =================
__global__ __launch_bounds__(NT, 8)
void u_kernel(const float* __restrict__ q,
              const float* __restrict__ fs,
              const float* __restrict__ Wq,
              const float* __restrict__ Wk) {
    __shared__ float spart[16 * DD];
    __shared__ float squ[DD];
    __shared__ float stmp[DD];

    const int b   = blockIdx.x;
    const int tid = threadIdx.x;
    const int hw  = tid >> 4;
    const int l16 = tid & 15;

    // qbar[d] = sum_f fs[f] * q[b,f,d]
    {
        const float4* qb4 = (const float4*)(q + (size_t)b * FF * DD);
        float4 a = make_float4(0.f, 0.f, 0.f, 0.f);
#pragma unroll
        for (int fi = 0; fi < 4; ++fi) {
            int f = hw + 16 * fi;
            float s = fs[f];
            float4 v = qb4[f * 16 + l16];
            a.x += s * v.x; a.y += s * v.y; a.z += s * v.z; a.w += s * v.w;
        }
        ((float4*)spart)[hw * 16 + l16] = a;
    }
    __syncthreads();
    if (tid < DD) {
        float s = 0.f;
#pragma unroll
        for (int i = 0; i < 16; ++i) s += spart[i * DD + tid];
        squ[tid] = s;
    }
    __syncthreads();

    // tmp[e] = sum_c qbar[c] * Wq[c,e]
    {
        float4 a = make_float4(0.f, 0.f, 0.f, 0.f);
#pragma unroll
        for (int ci = 0; ci < 4; ++ci) {
            int c = hw * 4 + ci;
            float s = squ[c];
            float4 v = ((const float4*)Wq)[c * 16 + l16];
            a.x += s * v.x; a.y += s * v.y; a.z += s * v.z; a.w += s * v.w;
        }
        ((float4*)spart)[hw * 16 + l16] = a;
    }
    __syncthreads();
    if (tid < DD) {
        float s = 0.f;
#pragma unroll
        for (int i = 0; i < 16; ++i) s += spart[i * DD + tid];
        stmp[tid] = s;
    }
    __syncthreads();

    // u[row] = sum_e tmp[e] * Wk[row,e]
    {
        float4 tv = ((const float4*)stmp)[l16];
#pragma unroll
        for (int r = 0; r < 4; ++r) {
            int row = hw + 16 * r;
            float4 wv = ((const float4*)(Wk + row * DD))[l16];
            float p = wv.x * tv.x + wv.y * tv.y + wv.z * tv.z + wv.w * tv.w;
#pragma unroll
            for (int o = 8; o; o >>= 1)
                p += __shfl_xor_sync(0xffffffffu, p, o);
            if (l16 == 0) g_u[b * DD + row] = p;
        }
    }
}

// ==== Kernel 2: pure-LDG fused streaming — no smem k, no cp.async ====
// Half-warp per row: coalesced float4 LDG, 13 independent loads per thread.
__global__ __launch_bounds__(NT, 6)
void score_kernel(const float* __restrict__ k,
                  const int*   __restrict__ kes_length,
                  const float* __restrict__ bias,
                  const float* __restrict__ Wv,
                  float*       __restrict__ out) {
    __shared__ float spart[16 * DD];       // half-warp partials
    __shared__ float su[DD];               // w
    __shared__ float sub[DD];              // u
    __shared__ float swr[16];              // exp-sums

    const int b   = blockIdx.x;
    const int tid = threadIdx.x;
    const int hw  = tid >> 4;              // half-warp id 0..15
    const int l16 = tid & 15;

    if (tid < 16)
        ((float4*)sub)[tid] = ((const float4*)(g_u + (size_t)b * DD))[tid];
    const int   len   = kes_length[b];
    const float biasD = bias[0] * (float)DD;
    const float mfill = (len == 0) ? 1.f : 0.f;
    __syncthreads();

    const float4  uv  = ((const float4*)sub)[l16];
    const float4* kb4 = (const float4*)(k + (size_t)b * KT);

    // ---- fused: load -> dot -> 16-lane reduce -> exp -> accumulate ----
    float4 wa   = make_float4(0.f, 0.f, 0.f, 0.f);
    float  esum = 0.f;
#pragma unroll
    for (int i = 0; i < 13; ++i) {
        int t = hw + (i << 4);             // rows hw, hw+16, ...
        if (t < MAXLEN) {
            float4 kv = kb4[t * 16 + l16]; // coalesced: half-warp spans 256B
            float p = kv.x * uv.x + kv.y * uv.y + kv.z * uv.z + kv.w * uv.w;
#pragma unroll
            for (int o = 8; o; o >>= 1)
                p += __shfl_xor_sync(0xffffffffu, p, o);
            float e = (t < len) ? fast_exp8(fast_sigmoid(p + biasD)) : mfill;
            wa.x += e * kv.x; wa.y += e * kv.y;
            wa.z += e * kv.z; wa.w += e * kv.w;
            esum += e;
        }
    }

    ((float4*)spart)[hw * 16 + l16] = wa;
    if (l16 == 0) swr[hw] = esum;
    __syncthreads();

    if (tid < DD) {
        float s = 0.f;
#pragma unroll
        for (int i = 0; i < 16; ++i) s += spart[i * DD + tid];
        su[tid] = s;
    }
    __syncthreads();

    // ---- out[b,e] = inv * sum_c w[c] * Wv[c,e] ----
    {
        float4 a = make_float4(0.f, 0.f, 0.f, 0.f);
#pragma unroll
        for (int ci = 0; ci < 4; ++ci) {
            int c = hw * 4 + ci;
            float s = su[c];
            float4 v = ((const float4*)Wv)[c * 16 + l16];
            a.x += s * v.x; a.y += s * v.y; a.z += s * v.z; a.w += s * v.w;
        }
        ((float4*)spart)[hw * 16 + l16] = a;
    }
    __syncthreads();
    if (tid < DD) {
        float tot = 0.f;
#pragma unroll
        for (int i = 0; i < 16; ++i) tot += swr[i];
        float s = 0.f;
#pragma unroll
        for (int i = 0; i < 16; ++i) s += spart[i * DD + tid];
        out[(size_t)b * DD + tid] = s * (1.f / tot);
    }
}

extern "C" void kernel_launch(void* const* d_in, const int* in_sizes, int n_in,
                              void* d_out, int out_size) {
    const float* q    = (const float*)d_in[0];
    const float* k    = (const float*)d_in[1];
    // d_in[2] = v : unused by the reference computation
    const int*   kes  = (const int*)  d_in[3];
    const float* fs   = (const float*)d_in[4];
    const float* bias = (const float*)d_in[5];
    const float* Wq   = (const float*)d_in[6];
    const float* Wk   = (const float*)d_in[7];
    const float* Wv   = (const float*)d_in[8];
    float*       out  = (float*)d_out;

    u_kernel<<<BB, NT>>>(q, fs, Wq, Wk);
    score_kernel<<<BB, NT>>>(k, kes, bias, Wv, out);
}

// round 15
// speedup vs baseline: 1.2182x; 1.0133x over previous
#include <cuda_runtime.h>
#include <cstdint>

#define BB      1024
#define MAXLEN  200
#define FF      64
#define DD      64
#define NT      256
#define KT      (MAXLEN * DD)              // 12800 floats per k tile

__device__ float g_u[BB * DD];             // 256 KB scratch: u per batch

__device__ __forceinline__ float fast_sigmoid(float x) {
    float t;
    asm("tanh.approx.f32 %0, %1;" : "=f"(t) : "f"(0.5f * x));
    return fmaf(0.5f, t, 0.5f);
}
__device__ __forceinline__ float fast_exp8(float x) {   // exp(x/8)
    float e;
    asm("ex2.approx.f32 %0, %1;" : "=f"(e) : "f"(x * 0.18033688011112042f));
    return e;
}

// ================= Kernel 1: u[b] = ((fs.q[b]) @ Wq) @ Wk^T =================
__global__ __launch_bounds__(NT, 8)
void u_kernel(const float* __restrict__ q,
              const float* __restrict__ fs,
              const float* __restrict__ Wq,
              const float* __restrict__ Wk) {
    __shared__ float spart[16 * DD];
    __shared__ float squ[DD];
    __shared__ float stmp[DD];

    const int b   = blockIdx.x;
    const int tid = threadIdx.x;
    const int hw  = tid >> 4;
    const int l16 = tid & 15;

    // qbar[d] = sum_f fs[f] * q[b,f,d]
    {
        const float4* qb4 = (const float4*)(q + (size_t)b * FF * DD);
        float4 a = make_float4(0.f, 0.f, 0.f, 0.f);
#pragma unroll
        for (int fi = 0; fi < 4; ++fi) {
            int f = hw + 16 * fi;
            float s = fs[f];
            float4 v = qb4[f * 16 + l16];
            a.x += s * v.x; a.y += s * v.y; a.z += s * v.z; a.w += s * v.w;
        }
        ((float4*)spart)[hw * 16 + l16] = a;
    }
    __syncthreads();
    if (tid < DD) {
        float s = 0.f;
#pragma unroll
        for (int i = 0; i < 16; ++i) s += spart[i * DD + tid];
        squ[tid] = s;
    }
    __syncthreads();

    // tmp[e] = sum_c qbar[c] * Wq[c,e]
    {
        float4 a = make_float4(0.f, 0.f, 0.f, 0.f);
#pragma unroll
        for (int ci = 0; ci < 4; ++ci) {
            int c = hw * 4 + ci;
            float s = squ[c];
            float4 v = ((const float4*)Wq)[c * 16 + l16];
            a.x += s * v.x; a.y += s * v.y; a.z += s * v.z; a.w += s * v.w;
        }
        ((float4*)spart)[hw * 16 + l16] = a;
    }
    __syncthreads();
    if (tid < DD) {
        float s = 0.f;
#pragma unroll
        for (int i = 0; i < 16; ++i) s += spart[i * DD + tid];
        stmp[tid] = s;
    }
    __syncthreads();

    // u[row] = sum_e tmp[e] * Wk[row,e]
    {
        float4 tv = ((const float4*)stmp)[l16];
#pragma unroll
        for (int r = 0; r < 4; ++r) {
            int row = hw + 16 * r;
            float4 wv = ((const float4*)(Wk + row * DD))[l16];
            float p = wv.x * tv.x + wv.y * tv.y + wv.z * tv.z + wv.w * tv.w;
#pragma unroll
            for (int o = 8; o; o >>= 1)
                p += __shfl_xor_sync(0xffffffffu, p, o);
            if (l16 == 0) g_u[b * DD + row] = p;
        }
    }
}

// ==== Kernel 2: register-resident k, shuffle-free, 1 MUFU-pair per row ====
__global__ __launch_bounds__(NT, 3)     // allow ~84 regs: 13 float4 stay live
void score_kernel(const float* __restrict__ k,
                  const int*   __restrict__ kes_length,
                  const float* __restrict__ bias,
                  const float* __restrict__ Wv,
                  float*       __restrict__ out) {
    __shared__ float sp[MAXLEN * 16];      // per-row 16 partial dots (12.8 KB)
    __shared__ float sa[MAXLEN];           // e values
    __shared__ float spart[16 * DD];       // half-warp float4 partials
    __shared__ float su[DD];               // w
    __shared__ float sub[DD];              // u
    __shared__ float swr[16];              // exp-sums

    const int b   = blockIdx.x;
    const int tid = threadIdx.x;
    const int hw  = tid >> 4;              // half-warp id 0..15
    const int l16 = tid & 15;

    if (tid < 16)
        ((float4*)sub)[tid] = ((const float4*)(g_u + (size_t)b * DD))[tid];
    const int   len   = kes_length[b];
    const float biasD = bias[0] * (float)DD;
    const float mfill = (len == 0) ? 1.f : 0.f;
    __syncthreads();

    const float4  uv  = ((const float4*)sub)[l16];
    const float4* kb4 = (const float4*)(k + (size_t)b * KT);

    // ---- phase 1: load k rows into registers, 4-wide partial dot, STS.32 ----
    float4 kreg[13];
#pragma unroll
    for (int i = 0; i < 13; ++i) {
        int t = hw + (i << 4);
        if (t < MAXLEN)
            kreg[i] = kb4[t * 16 + l16];   // coalesced, 13-deep MLP
    }
#pragma unroll
    for (int i = 0; i < 13; ++i) {
        int t = hw + (i << 4);
        if (t < MAXLEN) {
            float p = kreg[i].x * uv.x + kreg[i].y * uv.y
                    + kreg[i].z * uv.z + kreg[i].w * uv.w;
            sp[t * 16 + l16] = p;          // no shuffle
        }
    }
    __syncthreads();

    // ---- phase 2: one thread per row — reduce 16 partials, ONE sigmoid/exp ----
    if (tid < MAXLEN) {
        const float4* r = (const float4*)(sp + tid * 16);
        float4 a = r[0], c = r[1], d = r[2], f = r[3];
        float s = (((a.x + a.y) + (a.z + a.w)) + ((c.x + c.y) + (c.z + c.w)))
                + (((d.x + d.y) + (d.z + d.w)) + ((f.x + f.y) + (f.z + f.w)));
        sa[tid] = (tid < len) ? fast_exp8(fast_sigmoid(s + biasD)) : mfill;
    }
    __syncthreads();

    // ---- phase 3: weighted sum from REGISTER k, e via one broadcast LDS ----
    float4 wa   = make_float4(0.f, 0.f, 0.f, 0.f);
    float  esum = 0.f;
#pragma unroll
    for (int i = 0; i < 13; ++i) {
        int t = hw + (i << 4);
        if (t < MAXLEN) {
            float e = sa[t];               // broadcast within half-warp
            wa.x += e * kreg[i].x; wa.y += e * kreg[i].y;
            wa.z += e * kreg[i].z; wa.w += e * kreg[i].w;
            esum += e;
        }
    }
    ((float4*)spart)[hw * 16 + l16] = wa;
    if (l16 == 0) swr[hw] = esum;
    __syncthreads();

    if (tid < DD) {
        float s = 0.f;
#pragma unroll
        for (int i = 0; i < 16; ++i) s += spart[i * DD + tid];
        su[tid] = s;
    }
    __syncthreads();

    // ---- out[b,e] = inv * sum_c w[c] * Wv[c,e] ----
    {
        float4 a = make_float4(0.f, 0.f, 0.f, 0.f);
#pragma unroll
        for (int ci = 0; ci < 4; ++ci) {
            int c = hw * 4 + ci;
            float s = su[c];
            float4 v = ((const float4*)Wv)[c * 16 + l16];
            a.x += s * v.x; a.y += s * v.y; a.z += s * v.z; a.w += s * v.w;
        }
        ((float4*)spart)[hw * 16 + l16] = a;
    }
    __syncthreads();
    if (tid < DD) {
        float tot = 0.f;
#pragma unroll
        for (int i = 0; i < 16; ++i) tot += swr[i];
        float s = 0.f;
#pragma unroll
        for (int i = 0; i < 16; ++i) s += spart[i * DD + tid];
        out[(size_t)b * DD + tid] = s * (1.f / tot);
    }
}

extern "C" void kernel_launch(void* const* d_in, const int* in_sizes, int n_in,
                              void* d_out, int out_size) {
    const float* q    = (const float*)d_in[0];
    const float* k    = (const float*)d_in[1];
    // d_in[2] = v : unused by the reference computation
    const int*   kes  = (const int*)  d_in[3];
    const float* fs   = (const float*)d_in[4];
    const float* bias = (const float*)d_in[5];
    const float* Wq   = (const float*)d_in[6];
    const float* Wk   = (const float*)d_in[7];
    const float* Wv   = (const float*)d_in[8];
    float*       out  = (float*)d_out;

    u_kernel<<<BB, NT>>>(q, fs, Wq, Wk);
    score_kernel<<<BB, NT>>>(k, kes, bias, Wv, out);
}